// round 1
// baseline (speedup 1.0000x reference)
#include <cuda_runtime.h>

// ---------------- problem constants ----------------
#define CC      64
#define HH      120
#define WW      120
#define NBOX    8192
#define HID     128
#define SCOORD  (119.0f / 960.0f)   // (x/960*2-1 + 1) * 0.5 * 119  ==  x * 119/960

#define FIN_A   576
#define FIN_B   3136
#define FIN_C   7744
#define FIN_TOT (FIN_A + FIN_B + FIN_C)

// ---------------- device scratch (no allocs allowed) ----------------
__device__ float d_fmT[HH * WW * CC];          // [y][x][c]  3.69 MB
__device__ float d_W1T[FIN_TOT * HID];         // pos-major-permuted, transposed W1, 5.87 MB
__device__ float d_gf[CC];
__device__ float d_g[16];

// ---------------- f32x2 helpers (sm_100+ packed fp32) ----------------
__device__ __forceinline__ unsigned long long pack2(float x) {
    unsigned long long r;
    asm("mov.b64 %0, {%1, %1};" : "=l"(r) : "r"(__float_as_uint(x)));
    return r;
}
__device__ __forceinline__ void fma2(unsigned long long& d,
                                     unsigned long long a,
                                     unsigned long long b) {
    asm("fma.rn.f32x2 %0, %1, %2, %0;" : "+l"(d) : "l"(a), "l"(b));
}

// ---------------- prep kernels ----------------
// fm [C,H,W] -> fmT [H*W, C]
__global__ void transpose_fm_kernel(const float* __restrict__ fm) {
    int idx = blockIdx.x * 256 + threadIdx.x;          // < 921600
    int c = idx & 63;
    int p = idx >> 6;
    d_fmT[idx] = fm[c * (HH * WW) + p];
}

// W1 [128, fin] with k = c*r2+pos  ->  W1T[base + (pos*64+c)*128 + n]
__global__ void transpose_w1_kernel(const float* __restrict__ W1, int fin, int r2, int base) {
    int idx = blockIdx.x * 256 + threadIdx.x;
    if (idx >= fin * HID) return;
    int n   = idx & 127;
    int kp  = idx >> 7;       // k' = pos*64 + c
    int c   = kp & 63;
    int pos = kp >> 6;
    d_W1T[base + idx] = W1[n * fin + c * r2 + pos];
}

// per-channel spatial mean
__global__ void gf_kernel(const float* __restrict__ fm) {
    int c = blockIdx.x;
    float s = 0.0f;
    for (int i = threadIdx.x; i < HH * WW; i += 256) s += fm[c * (HH * WW) + i];
    __shared__ float red[8];
    #pragma unroll
    for (int off = 16; off; off >>= 1) s += __shfl_down_sync(0xffffffffu, s, off);
    if ((threadIdx.x & 31) == 0) red[threadIdx.x >> 5] = s;
    __syncthreads();
    if (threadIdx.x < 8) {
        s = red[threadIdx.x];
        #pragma unroll
        for (int off = 4; off; off >>= 1) s += __shfl_down_sync(0xffu, s, off);
        if (threadIdx.x == 0) d_gf[c] = s / (float)(HH * WW);
    }
}

__global__ void g_kernel(const float* __restrict__ Wg, const float* __restrict__ bg) {
    int j = threadIdx.x;   // 16 threads
    float s = bg[j];
    #pragma unroll 8
    for (int c = 0; c < CC; c++) s += d_gf[c] * Wg[j * CC + c];
    d_g[j] = s;
}

__global__ void g_write_kernel(float* __restrict__ out) {
    int idx = blockIdx.x * 256 + threadIdx.x;   // < 8192*16
    int m = idx >> 4;
    int j = idx & 15;
    out[m * 64 + 48 + j] = d_g[j];
}

// ---------------- fused head kernel ----------------
struct Pref {
    float4 t00, t01, t10, t11;
    float  w00, w01, w10, w11;
    float4 b0, b1;
};

__device__ __forceinline__ Pref do_prefetch(int kt, int r, float invr,
                                            const float* __restrict__ boxp,
                                            const float* __restrict__ w1t,
                                            int tid) {
    Pref p;
    int pos = kt >> 2;                 // 4 tiles of 16 channels per position
    int c0  = (kt & 3) << 4;
    int py  = pos / r;
    int px  = pos - py * r;
    float tx = px * invr;
    float ty = py * invr;

    int m    = tid >> 2;
    int cvec = c0 + ((tid & 3) << 2);

    const float4 bp = *reinterpret_cast<const float4*>(&boxp[m * 4]);
    // ix = ax + bx*tx  (all in [0,119] for in-image boxes; masked anyway)
    float ix = fmaf(bp.y, tx, bp.x);
    float iy = fmaf(bp.w, ty, bp.z);
    float x0f = floorf(ix), y0f = floorf(iy);
    float wx = ix - x0f, wy = iy - y0f;
    int x0 = (int)x0f, y0 = (int)y0f;
    int x1 = x0 + 1,   y1 = y0 + 1;
    float vx0 = (x0 >= 0 && x0 < WW) ? 1.0f : 0.0f;
    float vx1 = (x1 >= 0 && x1 < WW) ? 1.0f : 0.0f;
    float vy0 = (y0 >= 0 && y0 < HH) ? 1.0f : 0.0f;
    float vy1 = (y1 >= 0 && y1 < HH) ? 1.0f : 0.0f;
    p.w00 = (1.0f - wx) * (1.0f - wy) * vx0 * vy0;
    p.w01 = wx * (1.0f - wy) * vx1 * vy0;
    p.w10 = (1.0f - wx) * wy * vx0 * vy1;
    p.w11 = wx * wy * vx1 * vy1;
    int cx0 = min(max(x0, 0), WW - 1), cx1 = min(max(x1, 0), WW - 1);
    int cy0 = min(max(y0, 0), HH - 1), cy1 = min(max(y1, 0), HH - 1);

    const float4* f = reinterpret_cast<const float4*>(d_fmT);
    int cq = cvec >> 2;
    p.t00 = __ldg(&f[(cy0 * WW + cx0) * 16 + cq]);
    p.t01 = __ldg(&f[(cy0 * WW + cx1) * 16 + cq]);
    p.t10 = __ldg(&f[(cy1 * WW + cx0) * 16 + cq]);
    p.t11 = __ldg(&f[(cy1 * WW + cx1) * 16 + cq]);

    const float4* wb = reinterpret_cast<const float4*>(w1t + (size_t)kt * 16 * HID);
    p.b0 = __ldg(&wb[tid]);
    p.b1 = __ldg(&wb[tid + 256]);
    return p;
}

__global__ void __launch_bounds__(256, 2)
head_kernel(const float* __restrict__ boxes,
            const float* __restrict__ b1,
            const float* __restrict__ W2,
            const float* __restrict__ b2,
            const float* __restrict__ scale_w,
            float* __restrict__ out,
            int fin, int r, float invr, int od, int col0, int swidx, int w1tbase) {
    __shared__ float pool[8192];    // phase1: As[16*64] | Bs[16*128]; phase2: Hs[64*128]
    __shared__ float boxp[256];     // 64 boxes x (ax,bx,ay,by)
    float* As = pool;
    float* Bs = pool + 1024;
    float* Hs = pool;

    const int tid  = threadIdx.x;
    const int box0 = blockIdx.x * 64;

    if (tid < 64) {
        float4 b4 = __ldg(reinterpret_cast<const float4*>(boxes) + (box0 + tid));
        float4 o;
        o.x = b4.x * SCOORD;           // ax
        o.y = (b4.z - b4.x) * SCOORD;  // bx
        o.z = b4.y * SCOORD;           // ay
        o.w = (b4.w - b4.y) * SCOORD;  // by
        *reinterpret_cast<float4*>(&boxp[tid * 4]) = o;
    }
    __syncthreads();

    const float* w1t = d_W1T + w1tbase;
    const int ntiles = fin >> 4;

    unsigned long long acc[4][4];
    #pragma unroll
    for (int i = 0; i < 4; i++)
        #pragma unroll
        for (int j = 0; j < 4; j++) acc[i][j] = 0ull;

    const int m0 = (tid >> 4) << 2;   // 4 boxes per thread
    const int n0 = (tid & 15) << 3;   // 8 hidden per thread (4 f32x2 pairs)

    const int sm  = tid >> 2;          // im2col store: box index
    const int skl = (tid & 3) << 2;    // im2col store: local-k base (channel group)

    Pref p = do_prefetch(0, r, invr, boxp, w1t, tid);

    for (int kt = 0; kt < ntiles; ++kt) {
        // combine prefetched taps -> A tile (stored [k][m] for vector LDS)
        float4 v;
        v.x = p.w00 * p.t00.x + p.w01 * p.t01.x + p.w10 * p.t10.x + p.w11 * p.t11.x;
        v.y = p.w00 * p.t00.y + p.w01 * p.t01.y + p.w10 * p.t10.y + p.w11 * p.t11.y;
        v.z = p.w00 * p.t00.z + p.w01 * p.t01.z + p.w10 * p.t10.z + p.w11 * p.t11.z;
        v.w = p.w00 * p.t00.w + p.w01 * p.t01.w + p.w10 * p.t10.w + p.w11 * p.t11.w;
        As[(skl + 0) * 64 + sm] = v.x;
        As[(skl + 1) * 64 + sm] = v.y;
        As[(skl + 2) * 64 + sm] = v.z;
        As[(skl + 3) * 64 + sm] = v.w;
        *reinterpret_cast<float4*>(&Bs[tid * 4])        = p.b0;
        *reinterpret_cast<float4*>(&Bs[1024 + tid * 4]) = p.b1;
        __syncthreads();

        int ktn = (kt + 1 < ntiles) ? kt + 1 : kt;   // harmless re-fetch on last iter
        p = do_prefetch(ktn, r, invr, boxp, w1t, tid);

        #pragma unroll
        for (int k = 0; k < 16; k++) {
            float4 av = *reinterpret_cast<const float4*>(&As[k * 64 + m0]);
            ulonglong2 bv0 = *reinterpret_cast<const ulonglong2*>(&Bs[k * 128 + n0]);
            ulonglong2 bv1 = *reinterpret_cast<const ulonglong2*>(&Bs[k * 128 + n0 + 4]);
            unsigned long long a;
            a = pack2(av.x);
            fma2(acc[0][0], a, bv0.x); fma2(acc[0][1], a, bv0.y);
            fma2(acc[0][2], a, bv1.x); fma2(acc[0][3], a, bv1.y);
            a = pack2(av.y);
            fma2(acc[1][0], a, bv0.x); fma2(acc[1][1], a, bv0.y);
            fma2(acc[1][2], a, bv1.x); fma2(acc[1][3], a, bv1.y);
            a = pack2(av.z);
            fma2(acc[2][0], a, bv0.x); fma2(acc[2][1], a, bv0.y);
            fma2(acc[2][2], a, bv1.x); fma2(acc[2][3], a, bv1.y);
            a = pack2(av.w);
            fma2(acc[3][0], a, bv0.x); fma2(acc[3][1], a, bv0.y);
            fma2(acc[3][2], a, bv1.x); fma2(acc[3][3], a, bv1.y);
        }
        __syncthreads();
    }

    // layer-1 bias + relu -> Hs (aliases As/Bs, safe after trailing sync)
    float b1v[8];
    #pragma unroll
    for (int j = 0; j < 8; j++) b1v[j] = __ldg(&b1[n0 + j]);
    #pragma unroll
    for (int i = 0; i < 4; i++) {
        #pragma unroll
        for (int j = 0; j < 4; j++) {
            unsigned long long vij = acc[i][j];
            float f0 = __uint_as_float((unsigned int)vij)         + b1v[2 * j];
            float f1 = __uint_as_float((unsigned int)(vij >> 32)) + b1v[2 * j + 1];
            Hs[(m0 + i) * 128 + n0 + 2 * j]     = fmaxf(f0, 0.0f);
            Hs[(m0 + i) * 128 + n0 + 2 * j + 1] = fmaxf(f1, 0.0f);
        }
    }
    __syncthreads();

    // layer-2: out[m, col0+o] = relu(H[m,:] . W2[o,:] + b2[o]) * sw
    const float sw = __ldg(&scale_w[swidx]);
    const int njobs = od << 6;   // 64 * od
    for (int job = tid; job < njobs; job += 256) {
        int m = job / od;
        int o = job - m * od;
        float s = __ldg(&b2[o]);
        const float4* hrow = reinterpret_cast<const float4*>(&Hs[m * 128]);
        const float4* wrow = reinterpret_cast<const float4*>(&W2[o * 128]);
        #pragma unroll 8
        for (int q = 0; q < 32; q++) {
            float4 h4 = hrow[q];
            float4 w4 = __ldg(&wrow[q]);
            s += h4.x * w4.x + h4.y * w4.y + h4.z * w4.z + h4.w * w4.w;
        }
        out[(size_t)(box0 + m) * 64 + col0 + o] = fmaxf(s, 0.0f) * sw;
    }
}

// ---------------- launch ----------------
extern "C" void kernel_launch(void* const* d_in, const int* in_sizes, int n_in,
                              void* d_out, int out_size) {
    const float* fm      = (const float*)d_in[0];
    const float* boxes   = (const float*)d_in[1];
    const float* W1a     = (const float*)d_in[2];
    const float* b1a     = (const float*)d_in[3];
    const float* W2a     = (const float*)d_in[4];
    const float* b2a     = (const float*)d_in[5];
    const float* W1b     = (const float*)d_in[6];
    const float* b1b     = (const float*)d_in[7];
    const float* W2b     = (const float*)d_in[8];
    const float* b2b     = (const float*)d_in[9];
    const float* W1c     = (const float*)d_in[10];
    const float* b1c     = (const float*)d_in[11];
    const float* W2c     = (const float*)d_in[12];
    const float* b2c     = (const float*)d_in[13];
    const float* scale_w = (const float*)d_in[14];
    const float* Wg      = (const float*)d_in[15];
    const float* bg      = (const float*)d_in[16];
    float* out = (float*)d_out;

    // prep
    transpose_fm_kernel<<<(HH * WW * CC) / 256, 256>>>(fm);
    transpose_w1_kernel<<<(FIN_A * HID) / 256, 256>>>(W1a, FIN_A, 9, 0);
    transpose_w1_kernel<<<(FIN_B * HID) / 256, 256>>>(W1b, FIN_B, 49, FIN_A * HID);
    transpose_w1_kernel<<<(FIN_C * HID + 255) / 256, 256>>>(W1c, FIN_C, 121, (FIN_A + FIN_B) * HID);
    gf_kernel<<<CC, 256>>>(fm);
    g_kernel<<<1, 16>>>(Wg, bg);
    g_write_kernel<<<(NBOX * 16) / 256, 256>>>(out);

    // heads: a -> cols [0,22), b -> [22,43), c -> [43,48) (only 5 of 21 outputs kept)
    head_kernel<<<NBOX / 64, 256>>>(boxes, b1a, W2a, b2a, scale_w, out,
                                    FIN_A, 3, 0.5f, 22, 0, 0, 0);
    head_kernel<<<NBOX / 64, 256>>>(boxes, b1b, W2b, b2b, scale_w, out,
                                    FIN_B, 7, 1.0f / 6.0f, 21, 22, 1, FIN_A * HID);
    head_kernel<<<NBOX / 64, 256>>>(boxes, b1c, W2c, b2c, scale_w, out,
                                    FIN_C, 11, 0.1f, 5, 43, 2, (FIN_A + FIN_B) * HID);
}